// round 1
// baseline (speedup 1.0000x reference)
#include <cuda_runtime.h>
#include <cstdint>

#define DIM    768
#define KC     2048
#define NROWS  16384
#define BM     64
#define BN     128
#define BD     16
#define NDT    (DIM / BD)   // 48
#define NCT    (KC / BN)    // 16

__device__ float g_enorm[KC];
__device__ float g_zsum[NROWS];
__device__ float g_loss;

// ---------------- packed f32x2 helpers (Blackwell sm_103a) ----------------
static __device__ __forceinline__ unsigned long long pk2(float x, float y) {
    unsigned long long r;
    asm("mov.b64 %0, {%1, %2};" : "=l"(r) : "f"(x), "f"(y));
    return r;
}
static __device__ __forceinline__ void fma2(unsigned long long& d,
                                            unsigned long long a,
                                            unsigned long long b) {
    asm("fma.rn.f32x2 %0, %1, %2, %3;" : "=l"(d) : "l"(a), "l"(b), "l"(d));
}
static __device__ __forceinline__ void upk2(unsigned long long v, float& lo, float& hi) {
    asm("mov.b64 {%0, %1}, %2;" : "=f"(lo), "=f"(hi) : "l"(v));
}

// ---------------- row squared-norms (one warp per row) ----------------
__global__ void rownorm_kernel(const float* __restrict__ src, int nrows, int which) {
    int w    = (blockIdx.x * blockDim.x + threadIdx.x) >> 5;
    int lane = threadIdx.x & 31;
    if (w >= nrows) return;
    const float* row = src + (size_t)w * DIM;
    float s = 0.f;
#pragma unroll
    for (int i = 0; i < DIM / 32; i++) {
        float v = row[lane + i * 32];
        s = fmaf(v, v, s);
    }
#pragma unroll
    for (int o = 16; o > 0; o >>= 1) s += __shfl_down_sync(0xffffffffu, s, o);
    if (lane == 0) {
        if (which) g_zsum[w] = s;
        else       g_enorm[w] = s;
    }
}

__global__ void zero_loss_kernel() { g_loss = 0.f; }

// ---------------- main: fused score-GEMM + online argmin ----------------
// grid: NROWS/BM = 256 blocks, 256 threads.
// Thread (tx,ty): tx=tid&15 -> 8 codes, ty=tid>>4 -> 4 rows. f32x2 accumulators.
__global__ __launch_bounds__(256, 2)
void vq_argmin_kernel(const float* __restrict__ z,
                      const float* __restrict__ emb,
                      float* __restrict__ ids_out)
{
    __shared__ float zs[BD][BM + 4];
    __shared__ float es[BD][BN + 4];
    __shared__ float rv[BM][17];
    __shared__ int   ri[BM][17];

    const int tid     = threadIdx.x;
    const int tx      = tid & 15;
    const int ty      = tid >> 4;
    const int rowBase = blockIdx.x * BM;

    // gmem load assignments (float4 granularity)
    const int zrow  = tid >> 2;          // 0..63
    const int zc4w  = (tid & 3) * 4;     // 0,4,8,12
    const int erowA = tid >> 2;          // 0..63
    const int erowB = erowA + 64;        // 64..127
    const int ec4w  = (tid & 3) * 4;

    const float* zg = z + (size_t)(rowBase + zrow) * DIM + zc4w;

    unsigned long long acc[4][4];
#pragma unroll
    for (int i = 0; i < 4; i++)
#pragma unroll
        for (int j = 0; j < 4; j++) acc[i][j] = 0ull;

    float bestv[4];
    int   besti[4];
    float zr[4];
#pragma unroll
    for (int i = 0; i < 4; i++) {
        bestv[i] = 3.4e38f;
        besti[i] = 0;
        zr[i]    = g_zsum[rowBase + ty * 4 + i];
    }

    // register prefetch of first tile (ct=0, dt=0)
    float4 pz, pa, pb;
    pz = *(const float4*)(zg);
    {
        const float* eg = emb + ec4w;
        pa = *(const float4*)(eg + (size_t)erowA * DIM);
        pb = *(const float4*)(eg + (size_t)erowB * DIM);
    }

    int ct = 0, dt = 0;
    for (int it = 0; it < NCT * NDT; ++it) {
        // stage prefetched tile into smem (transposed: [d][row])
        zs[zc4w + 0][zrow] = pz.x;
        zs[zc4w + 1][zrow] = pz.y;
        zs[zc4w + 2][zrow] = pz.z;
        zs[zc4w + 3][zrow] = pz.w;
        es[ec4w + 0][erowA] = pa.x;
        es[ec4w + 1][erowA] = pa.y;
        es[ec4w + 2][erowA] = pa.z;
        es[ec4w + 3][erowA] = pa.w;
        es[ec4w + 0][erowB] = pb.x;
        es[ec4w + 1][erowB] = pb.y;
        es[ec4w + 2][erowB] = pb.z;
        es[ec4w + 3][erowB] = pb.w;
        __syncthreads();

        // prefetch next tile from gmem (hidden behind compute below)
        int ndt = dt + 1, nct = ct;
        if (ndt == NDT) { ndt = 0; nct = ct + 1; }
        if (nct < NCT) {
            pz = *(const float4*)(zg + ndt * BD);
            const float* eg = emb + ((size_t)nct * BN + erowA) * DIM + ndt * BD + ec4w;
            pa = *(const float4*)(eg);
            pb = *(const float4*)(eg + (size_t)64 * DIM);
        }

        // compute: 16 d-steps, 4x8 outer product per thread via f32x2
#pragma unroll
        for (int d = 0; d < BD; ++d) {
            float4 a4  = *(const float4*)&zs[d][ty * 4];
            float4 b4a = *(const float4*)&es[d][tx * 8];
            float4 b4b = *(const float4*)&es[d][tx * 8 + 4];
            unsigned long long aa[4], bb[4];
            aa[0] = pk2(a4.x, a4.x);
            aa[1] = pk2(a4.y, a4.y);
            aa[2] = pk2(a4.z, a4.z);
            aa[3] = pk2(a4.w, a4.w);
            bb[0] = pk2(b4a.x, b4a.y);
            bb[1] = pk2(b4a.z, b4a.w);
            bb[2] = pk2(b4b.x, b4b.y);
            bb[3] = pk2(b4b.z, b4b.w);
#pragma unroll
            for (int i = 0; i < 4; i++)
#pragma unroll
                for (int j = 0; j < 4; j++) fma2(acc[i][j], aa[i], bb[j]);
        }
        __syncthreads();

        // end of a code tile: fold scores into running argmin, reset acc
        if (dt == NDT - 1) {
            const int cbase = ct * BN + tx * 8;
            float en[8];
#pragma unroll
            for (int j = 0; j < 8; j++) en[j] = g_enorm[cbase + j];
#pragma unroll
            for (int i = 0; i < 4; i++) {
                float bv = bestv[i];
                int   bi = besti[i];
#pragma unroll
                for (int j = 0; j < 4; j++) {
                    float lo, hi;
                    upk2(acc[i][j], lo, hi);
                    acc[i][j] = 0ull;
                    // replicate reference rounding: (zsum + enorm) - 2*dot
                    float t0 = zr[i] + en[2 * j];
                    float t1 = zr[i] + en[2 * j + 1];
                    float s0 = t0 - 2.0f * lo;
                    float s1 = t1 - 2.0f * hi;
                    int c0 = cbase + 2 * j;
                    if (s0 < bv || (s0 == bv && c0 < bi))     { bv = s0; bi = c0; }
                    if (s1 < bv || (s1 == bv && c0 + 1 < bi)) { bv = s1; bi = c0 + 1; }
                }
                bestv[i] = bv;
                besti[i] = bi;
            }
        }
        dt = ndt;
        ct = nct;
    }

    // cross-thread reduction: 16 threads per row -> first-index argmin
#pragma unroll
    for (int i = 0; i < 4; i++) {
        rv[ty * 4 + i][tx] = bestv[i];
        ri[ty * 4 + i][tx] = besti[i];
    }
    __syncthreads();
    if (tid < BM) {
        float bv = rv[tid][0];
        int   bi = ri[tid][0];
#pragma unroll
        for (int t = 1; t < 16; t++) {
            float v = rv[tid][t];
            int   c = ri[tid][t];
            if (v < bv || (v == bv && c < bi)) { bv = v; bi = c; }
        }
        ids_out[rowBase + tid] = (float)bi;
    }
}

// ---------------- gather z_q + commitment-loss partial sums ----------------
__global__ void gather_loss_kernel(const float* __restrict__ z,
                                   const float* __restrict__ emb,
                                   const float* __restrict__ idsf,
                                   float* __restrict__ zq)
{
    const int D4 = DIM / 4;  // 192
    const long long total4 = (long long)NROWS * D4;
    float acc = 0.f;
    for (long long i = (long long)blockIdx.x * blockDim.x + threadIdx.x; i < total4;
         i += (long long)gridDim.x * blockDim.x) {
        int row = (int)(i / D4);
        int c4  = (int)(i - (long long)row * D4);
        int id  = (int)idsf[row];
        float4 q  = ((const float4*)emb)[(size_t)id * D4 + c4];
        float4 zv = ((const float4*)z)[i];
        ((float4*)zq)[i] = q;
        float d0 = zv.x - q.x, d1 = zv.y - q.y, d2 = zv.z - q.z, d3 = zv.w - q.w;
        acc += d0 * d0 + d1 * d1 + d2 * d2 + d3 * d3;
    }
#pragma unroll
    for (int o = 16; o > 0; o >>= 1) acc += __shfl_down_sync(0xffffffffu, acc, o);
    __shared__ float red[8];
    int lane = threadIdx.x & 31, wid = threadIdx.x >> 5;
    if (lane == 0) red[wid] = acc;
    __syncthreads();
    if (wid == 0) {
        float v = (lane < 8) ? red[lane] : 0.f;
#pragma unroll
        for (int o = 4; o > 0; o >>= 1) v += __shfl_down_sync(0xffffffffu, v, o);
        if (lane == 0) atomicAdd(&g_loss, v);
    }
}

__global__ void finalize_kernel(float* __restrict__ loss_out) {
    *loss_out = 0.25f * (g_loss / (float)((long long)NROWS * DIM));
}

// ---------------- launch ----------------
extern "C" void kernel_launch(void* const* d_in, const int* in_sizes, int n_in,
                              void* d_out, int out_size) {
    (void)in_sizes; (void)n_in; (void)out_size;
    const float* z   = (const float*)d_in[0];
    const float* emb = (const float*)d_in[1];
    float* out   = (float*)d_out;
    float* zq    = out;                              // [NROWS*DIM]
    float* idsf  = out + (size_t)NROWS * DIM;        // [NROWS]
    float* lossp = idsf + NROWS;                     // [1]

    rownorm_kernel<<<KC / 8, 256>>>(emb, KC, 0);
    rownorm_kernel<<<NROWS / 8, 256>>>(z, NROWS, 1);
    zero_loss_kernel<<<1, 1>>>();
    vq_argmin_kernel<<<NROWS / BM, 256>>>(z, emb, idsf);
    gather_loss_kernel<<<2048, 256>>>(z, emb, idsf, zq);
    finalize_kernel<<<1, 1>>>(lossp);
}

// round 3
// speedup vs baseline: 4.0157x; 4.0157x over previous
#include <cuda_runtime.h>
#include <cuda_bf16.h>
#include <cstdint>

#define DIM    768
#define KC     2048
#define NROWS  16384
#define BM     128
#define BN     128
#define BK     32
#define CHUNKS (DIM / BK)      // 24
#define NTILE  (KC / BN)       // 16
#define TOT    (NTILE * CHUNKS) // 384
#define STAGE_BYTES 32768       // A_hi 8K | A_lo 8K | B_hi 8K | B_lo 8K
#define NSTAGE 3

__device__ float g_enorm[KC];
__device__ float g_zsum[NROWS];
__device__ float g_loss;
__device__ __nv_bfloat16 g_zhi[(size_t)NROWS * DIM];
__device__ __nv_bfloat16 g_zlo[(size_t)NROWS * DIM];
__device__ __nv_bfloat16 g_ehi[(size_t)KC * DIM];
__device__ __nv_bfloat16 g_elo[(size_t)KC * DIM];

static __device__ __forceinline__ uint32_t smem_u32(const void* p) {
    uint32_t a;
    asm("{ .reg .u64 t; cvta.to.shared.u64 t, %1; cvt.u32.u64 %0, t; }" : "=r"(a) : "l"(p));
    return a;
}

#define CP_ASYNC16(dst, src) \
    asm volatile("cp.async.cg.shared.global [%0], [%1], 16;" :: "r"(dst), "l"(src))
#define CP_COMMIT() asm volatile("cp.async.commit_group;" ::: "memory")

#define LDMX4(r, addr) \
    asm volatile("ldmatrix.sync.aligned.m8n8.x4.shared.b16 {%0,%1,%2,%3}, [%4];" \
        : "=r"((r)[0]), "=r"((r)[1]), "=r"((r)[2]), "=r"((r)[3]) : "r"(addr))

#define MMA16816(d, a, b0_, b1_) \
    asm volatile("mma.sync.aligned.m16n8k16.row.col.f32.bf16.bf16.f32 " \
        "{%0,%1,%2,%3}, {%4,%5,%6,%7}, {%8,%9}, {%0,%1,%2,%3};" \
        : "+f"((d)[0]), "+f"((d)[1]), "+f"((d)[2]), "+f"((d)[3]) \
        : "r"((a)[0]), "r"((a)[1]), "r"((a)[2]), "r"((a)[3]), "r"(b0_), "r"(b1_))

// ---------------- bf16 hi/lo decomposition ----------------
__global__ void decompose_kernel(const float* __restrict__ src,
                                 __nv_bfloat16* __restrict__ hi,
                                 __nv_bfloat16* __restrict__ lo, int n4) {
    int i = blockIdx.x * blockDim.x + threadIdx.x;
    int stride = gridDim.x * blockDim.x;
    __nv_bfloat162* hp = (__nv_bfloat162*)hi;
    __nv_bfloat162* lp = (__nv_bfloat162*)lo;
    for (; i < n4; i += stride) {
        float4 v = ((const float4*)src)[i];
        __nv_bfloat16 h0 = __float2bfloat16_rn(v.x);
        __nv_bfloat16 h1 = __float2bfloat16_rn(v.y);
        __nv_bfloat16 h2 = __float2bfloat16_rn(v.z);
        __nv_bfloat16 h3 = __float2bfloat16_rn(v.w);
        __nv_bfloat16 l0 = __float2bfloat16_rn(v.x - __bfloat162float(h0));
        __nv_bfloat16 l1 = __float2bfloat16_rn(v.y - __bfloat162float(h1));
        __nv_bfloat16 l2 = __float2bfloat16_rn(v.z - __bfloat162float(h2));
        __nv_bfloat16 l3 = __float2bfloat16_rn(v.w - __bfloat162float(h3));
        hp[2 * i]     = __halves2bfloat162(h0, h1);
        hp[2 * i + 1] = __halves2bfloat162(h2, h3);
        lp[2 * i]     = __halves2bfloat162(l0, l1);
        lp[2 * i + 1] = __halves2bfloat162(l2, l3);
    }
}

// ---------------- row squared-norms (one warp per row) ----------------
__global__ void rownorm_kernel(const float* __restrict__ src, int nrows, int which) {
    int w    = (blockIdx.x * blockDim.x + threadIdx.x) >> 5;
    int lane = threadIdx.x & 31;
    if (w >= nrows) return;
    const float* row = src + (size_t)w * DIM;
    float s = 0.f;
#pragma unroll
    for (int i = 0; i < DIM / 32; i++) {
        float v = row[lane + i * 32];
        s = fmaf(v, v, s);
    }
#pragma unroll
    for (int o = 16; o > 0; o >>= 1) s += __shfl_down_sync(0xffffffffu, s, o);
    if (lane == 0) {
        if (which) g_zsum[w] = s;
        else       g_enorm[w] = s;
    }
}

__global__ void zero_loss_kernel() { g_loss = 0.f; }

// ---------------- HMMA fused score-GEMM + argmin ----------------
// 128 CTAs x 256 threads. CTA: 128 rows x 2048 codes, K=768 streamed.
// Warps 2x4; warp tile 64x32 (4 m-tiles x 4 n-tiles of m16n8k16).
__global__ __launch_bounds__(256, 1)
void vq_mma_kernel(float* __restrict__ ids_out) {
    extern __shared__ char smem_raw[];
    const uint32_t sb = (smem_u32(smem_raw) + 127u) & ~127u;
    const int tid  = threadIdx.x;
    const int lane = tid & 31;
    const int w    = tid >> 5;
    const int wr   = w >> 2;   // 0..1 (row half)
    const int wc   = w & 3;    // 0..3 (code quarter)
    const int rowBase = blockIdx.x * BM;

    // ---- cp.async assignments: 8 x 16B per thread per stage ----
    uint32_t sdst[8];
    const __nv_bfloat16* gbase[8];
    bool isB[8];
#pragma unroll
    for (int i = 0; i < 8; i++) {
        int idx = i * 256 + tid;
        int part  = idx >> 10;        // 0 = A(z), 1 = B(e)
        int split = (idx >> 9) & 1;   // 0 = hi, 1 = lo
        int ww = idx & 511;
        int r  = ww >> 2;             // row 0..127
        int g  = ww & 3;              // 16B granule 0..3
        sdst[i] = (uint32_t)((part * 2 + split) * 8192 + r * 64 +
                             ((g ^ ((r >> 1) & 3)) << 4));
        const __nv_bfloat16* base =
            part ? (split ? g_elo : g_ehi) : (split ? g_zlo : g_zhi);
        gbase[i] = base + (size_t)(part ? r : (rowBase + r)) * DIM + g * 8;
        isB[i] = (part != 0);
    }

    // ---- ldmatrix lane addressing ----
    const int arow = lane & 15;                       // A row within m16
    const int agr  = lane >> 4;                       // A granule add (k+8)
    const int brow = (lane & 7) + ((lane >> 4) & 1) * 8;  // B row within n16
    const int bgr  = (lane >> 3) & 1;                 // B granule add (k+8)
    uint32_t a_rt[4]; int a_sw[4];
#pragma unroll
    for (int mt = 0; mt < 4; mt++) {
        int r = wr * 64 + mt * 16 + arow;
        a_rt[mt] = r * 64; a_sw[mt] = (r >> 1) & 3;
    }
    uint32_t b_rt[2]; int b_sw[2];
#pragma unroll
    for (int nh = 0; nh < 2; nh++) {
        int r = wc * 32 + nh * 16 + brow;
        b_rt[nh] = r * 64; b_sw[nh] = (r >> 1) & 3;
    }

    float acc[4][4][4];
#pragma unroll
    for (int mt = 0; mt < 4; mt++)
#pragma unroll
        for (int nt = 0; nt < 4; nt++)
#pragma unroll
            for (int q = 0; q < 4; q++) acc[mt][nt][q] = 0.f;

    float zr8[8];
#pragma unroll
    for (int ri = 0; ri < 8; ri++)
        zr8[ri] = g_zsum[rowBase + wr * 64 + (ri >> 1) * 16 + (ri & 1) * 8 + (lane >> 2)];

    float bv[8]; int bi[8];
#pragma unroll
    for (int ri = 0; ri < 8; ri++) { bv[ri] = 3.4e38f; bi[ri] = 0; }

    auto issue = [&](int ct, int c, int buf) {
        uint32_t st = sb + buf * STAGE_BYTES;
        size_t k0 = (size_t)c * BK;
        size_t bo = (size_t)ct * BN * DIM + k0;
#pragma unroll
        for (int i = 0; i < 8; i++) {
            const __nv_bfloat16* src = gbase[i] + (isB[i] ? bo : k0);
            CP_ASYNC16(st + sdst[i], src);
        }
        CP_COMMIT();
    };

    issue(0, 0, 0);
    issue(0, 1, 1);
    int ict = 0, icc = 2;   // next stage to issue = s+2
    int cct = 0, ccc = 0;   // current compute (ct, c)

    for (int s = 0; s < TOT; s++) {
        if (s == TOT - 1) asm volatile("cp.async.wait_group 0;" ::: "memory");
        else              asm volatile("cp.async.wait_group 1;" ::: "memory");
        __syncthreads();
        if (s + 2 < TOT) {
            issue(ict, icc, (s + 2) % NSTAGE);
            if (++icc == CHUNKS) { icc = 0; ++ict; }
        }

        const uint32_t Ah = sb + (s % NSTAGE) * STAGE_BYTES;
        const uint32_t Al = Ah + 8192;
        const uint32_t Bh = Ah + 16384;
        const uint32_t Bl = Ah + 24576;

#pragma unroll
        for (int ks = 0; ks < 2; ks++) {
            const int g0 = ks * 2;
            uint32_t ah[16], al[16], bh[8], bl[8];
#pragma unroll
            for (int mt = 0; mt < 4; mt++) {
                uint32_t ad = Ah + a_rt[mt] + (uint32_t)(((g0 + agr) ^ a_sw[mt]) << 4);
                LDMX4(&ah[mt * 4], ad);
            }
#pragma unroll
            for (int nh = 0; nh < 2; nh++) {
                uint32_t off = b_rt[nh] + (uint32_t)(((g0 + bgr) ^ b_sw[nh]) << 4);
                LDMX4(&bh[nh * 4], Bh + off);
                LDMX4(&bl[nh * 4], Bl + off);
            }
#pragma unroll
            for (int mt = 0; mt < 4; mt++)
#pragma unroll
                for (int nt = 0; nt < 4; nt++) {
                    const int bo_ = (nt >> 1) * 4 + (nt & 1) * 2;
                    MMA16816(acc[mt][nt], &ah[mt * 4], bh[bo_], bh[bo_ + 1]);
                    MMA16816(acc[mt][nt], &ah[mt * 4], bl[bo_], bl[bo_ + 1]);
                }
#pragma unroll
            for (int mt = 0; mt < 4; mt++) {
                uint32_t ad = Al + a_rt[mt] + (uint32_t)(((g0 + agr) ^ a_sw[mt]) << 4);
                LDMX4(&al[mt * 4], ad);
            }
#pragma unroll
            for (int mt = 0; mt < 4; mt++)
#pragma unroll
                for (int nt = 0; nt < 4; nt++) {
                    const int bo_ = (nt >> 1) * 4 + (nt & 1) * 2;
                    MMA16816(acc[mt][nt], &al[mt * 4], bh[bo_], bh[bo_ + 1]);
                }
        }

        // ---- per-code-tile epilogue: fold into running argmin ----
        if (ccc == CHUNKS - 1) {
#pragma unroll
            for (int nt = 0; nt < 4; nt++) {
                int n0 = cct * BN + wc * 32 + nt * 8 + (lane & 3) * 2;
                float e0 = __ldg(&g_enorm[n0]);
                float e1 = __ldg(&g_enorm[n0 + 1]);
#pragma unroll
                for (int mt = 0; mt < 4; mt++)
#pragma unroll
                    for (int h = 0; h < 2; h++) {
                        int ri = mt * 2 + h;
                        // reference rounding: fl(fl(zsum+enorm) - 2*dot)
                        float s0 = (zr8[ri] + e0) - 2.0f * acc[mt][nt][h * 2 + 0];
                        float s1 = (zr8[ri] + e1) - 2.0f * acc[mt][nt][h * 2 + 1];
                        if (s0 < bv[ri]) { bv[ri] = s0; bi[ri] = n0; }
                        if (s1 < bv[ri]) { bv[ri] = s1; bi[ri] = n0 + 1; }
                        acc[mt][nt][h * 2 + 0] = 0.f;
                        acc[mt][nt][h * 2 + 1] = 0.f;
                    }
            }
        }
        if (++ccc == CHUNKS) { ccc = 0; ++cct; }
    }

    // ---- cross-thread argmin reduction (first-index ties) ----
#pragma unroll
    for (int off = 1; off < 4; off <<= 1) {
#pragma unroll
        for (int ri = 0; ri < 8; ri++) {
            float vv = __shfl_xor_sync(0xffffffffu, bv[ri], off);
            int   ii = __shfl_xor_sync(0xffffffffu, bi[ri], off);
            if (vv < bv[ri] || (vv == bv[ri] && ii < bi[ri])) { bv[ri] = vv; bi[ri] = ii; }
        }
    }
    __syncthreads();
    float* redv = (float*)smem_raw;
    int*   redi = (int*)(smem_raw + 2048);
    if ((lane & 3) == 0) {
#pragma unroll
        for (int ri = 0; ri < 8; ri++) {
            int row = wr * 64 + (ri >> 1) * 16 + (ri & 1) * 8 + (lane >> 2);
            redv[row * 4 + wc] = bv[ri];
            redi[row * 4 + wc] = bi[ri];
        }
    }
    __syncthreads();
    if (tid < BM) {
        float v = redv[tid * 4]; int b = redi[tid * 4];
#pragma unroll
        for (int t = 1; t < 4; t++) {
            float vv = redv[tid * 4 + t]; int ii = redi[tid * 4 + t];
            if (vv < v || (vv == v && ii < b)) { v = vv; b = ii; }
        }
        ids_out[rowBase + tid] = (float)b;
    }
}

// ---------------- gather z_q + commitment-loss partial sums ----------------
__global__ void gather_loss_kernel(const float* __restrict__ z,
                                   const float* __restrict__ emb,
                                   const float* __restrict__ idsf,
                                   float* __restrict__ zq)
{
    const int D4 = DIM / 4;  // 192
    const long long total4 = (long long)NROWS * D4;
    float acc = 0.f;
    for (long long i = (long long)blockIdx.x * blockDim.x + threadIdx.x; i < total4;
         i += (long long)gridDim.x * blockDim.x) {
        int row = (int)(i / D4);
        int c4  = (int)(i - (long long)row * D4);
        int id  = (int)idsf[row];
        float4 q  = ((const float4*)emb)[(size_t)id * D4 + c4];
        float4 zv = ((const float4*)z)[i];
        ((float4*)zq)[i] = q;
        float d0 = zv.x - q.x, d1 = zv.y - q.y, d2 = zv.z - q.z, d3 = zv.w - q.w;
        acc += d0 * d0 + d1 * d1 + d2 * d2 + d3 * d3;
    }
#pragma unroll
    for (int o = 16; o > 0; o >>= 1) acc += __shfl_down_sync(0xffffffffu, acc, o);
    __shared__ float red[8];
    int lane = threadIdx.x & 31, wid = threadIdx.x >> 5;
    if (lane == 0) red[wid] = acc;
    __syncthreads();
    if (wid == 0) {
        float v = (lane < 8) ? red[lane] : 0.f;
#pragma unroll
        for (int o = 4; o > 0; o >>= 1) v += __shfl_down_sync(0xffffffffu, v, o);
        if (lane == 0) atomicAdd(&g_loss, v);
    }
}

__global__ void finalize_kernel(float* __restrict__ loss_out) {
    *loss_out = 0.25f * (g_loss / (float)((long long)NROWS * DIM));
}

// ---------------- launch ----------------
extern "C" void kernel_launch(void* const* d_in, const int* in_sizes, int n_in,
                              void* d_out, int out_size) {
    (void)in_sizes; (void)n_in; (void)out_size;
    const float* z   = (const float*)d_in[0];
    const float* emb = (const float*)d_in[1];
    float* out   = (float*)d_out;
    float* zq    = out;                              // [NROWS*DIM]
    float* idsf  = out + (size_t)NROWS * DIM;        // [NROWS]
    float* lossp = idsf + NROWS;                     // [1]

    __nv_bfloat16 *zhi_p, *zlo_p, *ehi_p, *elo_p;
    cudaGetSymbolAddress((void**)&zhi_p, g_zhi);
    cudaGetSymbolAddress((void**)&zlo_p, g_zlo);
    cudaGetSymbolAddress((void**)&ehi_p, g_ehi);
    cudaGetSymbolAddress((void**)&elo_p, g_elo);

    const int VQ_SMEM = NSTAGE * STAGE_BYTES + 256;
    cudaFuncSetAttribute(vq_mma_kernel, cudaFuncAttributeMaxDynamicSharedMemorySize, VQ_SMEM);

    decompose_kernel<<<2048, 256>>>(z, zhi_p, zlo_p, NROWS * DIM / 4);
    decompose_kernel<<<1536, 256>>>(emb, ehi_p, elo_p, KC * DIM / 4);
    rownorm_kernel<<<KC / 8, 256>>>(emb, KC, 0);
    rownorm_kernel<<<NROWS / 8, 256>>>(z, NROWS, 1);
    zero_loss_kernel<<<1, 1>>>();
    vq_mma_kernel<<<NROWS / BM, 256, VQ_SMEM>>>(idsf);
    gather_loss_kernel<<<2048, 256>>>(z, emb, idsf, zq);
    finalize_kernel<<<1, 1>>>(lossp);
}

// round 4
// speedup vs baseline: 6.7370x; 1.6777x over previous
#include <cuda_runtime.h>
#include <cuda_bf16.h>
#include <cstdint>

#define DIM    768
#define KC     2048
#define NROWS  16384
#define BM     64
#define BN     256
#define BK     32
#define CHUNKS (DIM / BK)        // 24
#define NTILE  (KC / BN)         // 8
#define TOT    (NTILE * CHUNKS)  // 192
#define STAGE  20480             // A 4KB + B 16KB
#define NSTAGE 4
#define MARGIN 5e-4f

__device__ float g_enorm[KC];
__device__ float g_zsum[NROWS];
__device__ float g_loss;
__device__ __nv_bfloat16 g_zhi[(size_t)NROWS * DIM];
__device__ __nv_bfloat16 g_ehi[(size_t)KC * DIM];
__device__ float g_dots[(size_t)NROWS * KC];   // 128 MiB approx dots

static __device__ __forceinline__ uint32_t smem_u32(const void* p) {
    uint32_t a;
    asm("{ .reg .u64 t; cvta.to.shared.u64 t, %1; cvt.u32.u64 %0, t; }" : "=r"(a) : "l"(p));
    return a;
}
#define CP_ASYNC16(dst, src) \
    asm volatile("cp.async.cg.shared.global [%0], [%1], 16;" :: "r"(dst), "l"(src))
#define CP_COMMIT() asm volatile("cp.async.commit_group;" ::: "memory")
#define LDMX4(r, addr) \
    asm volatile("ldmatrix.sync.aligned.m8n8.x4.shared.b16 {%0,%1,%2,%3}, [%4];" \
        : "=r"((r)[0]), "=r"((r)[1]), "=r"((r)[2]), "=r"((r)[3]) : "r"(addr))
#define MMA16816(d, a, b0_, b1_) \
    asm volatile("mma.sync.aligned.m16n8k16.row.col.f32.bf16.bf16.f32 " \
        "{%0,%1,%2,%3}, {%4,%5,%6,%7}, {%8,%9}, {%0,%1,%2,%3};" \
        : "+f"((d)[0]), "+f"((d)[1]), "+f"((d)[2]), "+f"((d)[3]) \
        : "r"((a)[0]), "r"((a)[1]), "r"((a)[2]), "r"((a)[3]), "r"(b0_), "r"(b1_))

// ---------------- fp32 -> bf16 convert ----------------
__global__ void tobf16_kernel(const float* __restrict__ src,
                              __nv_bfloat16* __restrict__ dst, int n4) {
    int i = blockIdx.x * blockDim.x + threadIdx.x;
    int stride = gridDim.x * blockDim.x;
    __nv_bfloat162* dp = (__nv_bfloat162*)dst;
    for (; i < n4; i += stride) {
        float4 v = ((const float4*)src)[i];
        dp[2 * i]     = __halves2bfloat162(__float2bfloat16_rn(v.x), __float2bfloat16_rn(v.y));
        dp[2 * i + 1] = __halves2bfloat162(__float2bfloat16_rn(v.z), __float2bfloat16_rn(v.w));
    }
}

// ---------------- row squared-norms (identical to prior rounds) ----------------
__global__ void rownorm_kernel(const float* __restrict__ src, int nrows, int which) {
    int w    = (blockIdx.x * blockDim.x + threadIdx.x) >> 5;
    int lane = threadIdx.x & 31;
    if (w >= nrows) return;
    const float* row = src + (size_t)w * DIM;
    float s = 0.f;
#pragma unroll
    for (int i = 0; i < DIM / 32; i++) {
        float v = row[lane + i * 32];
        s = fmaf(v, v, s);
    }
#pragma unroll
    for (int o = 16; o > 0; o >>= 1) s += __shfl_down_sync(0xffffffffu, s, o);
    if (lane == 0) {
        if (which) g_zsum[w] = s;
        else       g_enorm[w] = s;
    }
}

__global__ void zero_loss_kernel() { g_loss = 0.f; }

// ---------------- pass 1: approx dot GEMM (bf16 hi x hi) ----------------
// 256 CTAs x 256 thr. CTA: 64 rows x 2048 codes. Warps 2x4, warp tile 32x64.
__global__ __launch_bounds__(256, 2)
void vq_pass1_kernel() {
    extern __shared__ char smem_raw[];
    const uint32_t sb = (smem_u32(smem_raw) + 127u) & ~127u;
    const int tid  = threadIdx.x;
    const int lane = tid & 31;
    const int w    = tid >> 5;
    const int wr   = w >> 2;    // 0..1  rows 32 each
    const int wc   = w & 3;     // 0..3  cols 64 each
    const int rowBase = blockIdx.x * BM;

    // ---- cp.async: 5 x 16B per thread per stage (A 256 granules, B 1024) ----
    uint32_t sdst[5];
    const __nv_bfloat16* gptr[5];
    bool isB[5];
#pragma unroll
    for (int i = 0; i < 5; i++) {
        int idx = i * 256 + tid;
        if (idx < 256) {
            int r = idx >> 2, g = idx & 3;
            sdst[i] = (uint32_t)(r * 64 + ((g ^ ((r >> 1) & 3)) << 4));
            gptr[i] = g_zhi + (size_t)(rowBase + r) * DIM + g * 8;
            isB[i] = false;
        } else {
            int j = idx - 256;
            int r = j >> 2, g = j & 3;
            sdst[i] = (uint32_t)(4096 + r * 64 + ((g ^ ((r >> 1) & 3)) << 4));
            gptr[i] = g_ehi + (size_t)r * DIM + g * 8;
            isB[i] = true;
        }
    }

    // ---- ldmatrix lane addressing ----
    const int arow = lane & 15;
    const int agr  = lane >> 4;
    const int brow = (lane & 7) + ((lane >> 4) & 1) * 8;
    const int bgr  = (lane >> 3) & 1;
    uint32_t a_rt[2]; int a_sw[2];
#pragma unroll
    for (int mt = 0; mt < 2; mt++) {
        int r = wr * 32 + mt * 16 + arow;
        a_rt[mt] = r * 64; a_sw[mt] = (r >> 1) & 3;
    }
    uint32_t b_rt[4]; int b_sw[4];
#pragma unroll
    for (int nh = 0; nh < 4; nh++) {
        int r = wc * 64 + nh * 16 + brow;
        b_rt[nh] = r * 64; b_sw[nh] = (r >> 1) & 3;
    }

    float acc[2][8][4];
#pragma unroll
    for (int mt = 0; mt < 2; mt++)
#pragma unroll
        for (int nt = 0; nt < 8; nt++)
#pragma unroll
            for (int q = 0; q < 4; q++) acc[mt][nt][q] = 0.f;

    auto issue = [&](int ct, int c, int buf) {
        uint32_t st = sb + buf * STAGE;
        size_t k0 = (size_t)c * BK;
        size_t bo = (size_t)ct * BN * DIM + k0;
#pragma unroll
        for (int i = 0; i < 5; i++) {
            const __nv_bfloat16* src = gptr[i] + (isB[i] ? bo : k0);
            CP_ASYNC16(st + sdst[i], src);
        }
        CP_COMMIT();
    };

    issue(0, 0, 0);
    issue(0, 1, 1);
    issue(0, 2, 2);
    int cct = 0, ccc = 0;

    for (int s = 0; s < TOT; s++) {
        if (s >= TOT - 3) asm volatile("cp.async.wait_group 0;" ::: "memory");
        else              asm volatile("cp.async.wait_group 2;" ::: "memory");
        __syncthreads();
        int nx = s + 3;
        if (nx < TOT) issue(nx / CHUNKS, nx % CHUNKS, nx & 3);

        const uint32_t Ab = sb + (s & 3) * STAGE;
        const uint32_t Bb = Ab + 4096;

#pragma unroll
        for (int ks = 0; ks < 2; ks++) {
            const int g0 = ks * 2;
            uint32_t ah[8], bh[16];
#pragma unroll
            for (int mt = 0; mt < 2; mt++) {
                uint32_t ad = Ab + a_rt[mt] + (uint32_t)(((g0 + agr) ^ a_sw[mt]) << 4);
                LDMX4(&ah[mt * 4], ad);
            }
#pragma unroll
            for (int nh = 0; nh < 4; nh++) {
                uint32_t bd = Bb + b_rt[nh] + (uint32_t)(((g0 + bgr) ^ b_sw[nh]) << 4);
                LDMX4(&bh[nh * 4], bd);
            }
#pragma unroll
            for (int mt = 0; mt < 2; mt++)
#pragma unroll
                for (int nt = 0; nt < 8; nt++) {
                    const int bo_ = (nt >> 1) * 4 + (nt & 1) * 2;
                    MMA16816(acc[mt][nt], &ah[mt * 4], bh[bo_], bh[bo_ + 1]);
                }
        }

        // ---- tile end: store approx dots, reset acc ----
        if (ccc == CHUNKS - 1) {
#pragma unroll
            for (int mt = 0; mt < 2; mt++)
#pragma unroll
                for (int nt = 0; nt < 8; nt++) {
                    int colb = cct * BN + wc * 64 + nt * 8 + (lane & 3) * 2;
                    int row0 = rowBase + wr * 32 + mt * 16 + (lane >> 2);
#pragma unroll
                    for (int h = 0; h < 2; h++) {
                        float2 v = make_float2(acc[mt][nt][h * 2], acc[mt][nt][h * 2 + 1]);
                        *(float2*)&g_dots[(size_t)(row0 + h * 8) * KC + colb] = v;
                        acc[mt][nt][h * 2] = 0.f;
                        acc[mt][nt][h * 2 + 1] = 0.f;
                    }
                }
        }
        if (++ccc == CHUNKS) { ccc = 0; ++cct; }
    }
}

// ---------------- pass 2: scan + exact refine + gather + loss ----------------
// 2048 blocks x 256 thr; warp per row.
__global__ __launch_bounds__(256)
void refine_kernel(const float* __restrict__ z, const float* __restrict__ emb,
                   float* __restrict__ ids_out, float* __restrict__ zq) {
    __shared__ float en_s[KC];
    __shared__ float redl[8];
    for (int i = threadIdx.x; i < KC; i += 256) en_s[i] = g_enorm[i];
    __syncthreads();

    const int w    = threadIdx.x >> 5;
    const int lane = threadIdx.x & 31;
    const int r    = blockIdx.x * 8 + w;
    const float* drow = g_dots + (size_t)r * KC;
    const float zr = g_zsum[r];

    // cache z row across the warp (exact fp32)
    float zreg[24];
    const float* zrow = z + (size_t)r * DIM;
#pragma unroll
    for (int j = 0; j < 24; j++) zreg[j] = zrow[lane + j * 32];

    // scan 1: approx min
    float m = 3.4e38f;
#pragma unroll 4
    for (int k = 0; k < 64; k++) {
        float s = (zr + en_s[k * 32 + lane]) - 2.0f * drow[k * 32 + lane];
        m = fminf(m, s);
    }
#pragma unroll
    for (int o = 16; o > 0; o >>= 1) m = fminf(m, __shfl_xor_sync(0xffffffffu, m, o));
    const float thresh = m + MARGIN;

    // scan 2: candidates -> exact fp32 score, first-index tie-break
    float best = 3.4e38f;
    int   bi   = 0;
    for (int k = 0; k < 64; k++) {
        int c = k * 32 + lane;
        float s = (zr + en_s[c]) - 2.0f * drow[c];
        unsigned mask = __ballot_sync(0xffffffffu, s < thresh);
        while (mask) {
            int l = __ffs(mask) - 1;
            mask &= mask - 1;
            int cc = k * 32 + l;
            const float* erow = emb + (size_t)cc * DIM;
            float d = 0.f;
#pragma unroll
            for (int j = 0; j < 24; j++) d = fmaf(zreg[j], erow[lane + j * 32], d);
#pragma unroll
            for (int o = 16; o > 0; o >>= 1) d += __shfl_xor_sync(0xffffffffu, d, o);
            float se = (zr + en_s[cc]) - 2.0f * d;   // fl(t - 2*dot), matches ref
            if (se < best || (se == best && cc < bi)) { best = se; bi = cc; }
        }
    }

    // gather z_q + commitment-loss partial
    const float* erow = emb + (size_t)bi * DIM;
    float* qrow = zq + (size_t)r * DIM;
    float lacc = 0.f;
#pragma unroll
    for (int j = 0; j < 24; j++) {
        float q = erow[lane + j * 32];
        qrow[lane + j * 32] = q;
        float dd = zreg[j] - q;
        lacc = fmaf(dd, dd, lacc);
    }
#pragma unroll
    for (int o = 16; o > 0; o >>= 1) lacc += __shfl_down_sync(0xffffffffu, lacc, o);
    if (lane == 0) {
        ids_out[r] = (float)bi;
        redl[w] = lacc;
    }
    __syncthreads();
    if (threadIdx.x == 0) {
        float t = 0.f;
#pragma unroll
        for (int i = 0; i < 8; i++) t += redl[i];
        atomicAdd(&g_loss, t);
    }
}

__global__ void finalize_kernel(float* __restrict__ loss_out) {
    *loss_out = 0.25f * (g_loss / (float)((long long)NROWS * DIM));
}

// ---------------- launch ----------------
extern "C" void kernel_launch(void* const* d_in, const int* in_sizes, int n_in,
                              void* d_out, int out_size) {
    (void)in_sizes; (void)n_in; (void)out_size;
    const float* z   = (const float*)d_in[0];
    const float* emb = (const float*)d_in[1];
    float* out   = (float*)d_out;
    float* zq    = out;                              // [NROWS*DIM]
    float* idsf  = out + (size_t)NROWS * DIM;        // [NROWS]
    float* lossp = idsf + NROWS;                     // [1]

    __nv_bfloat16 *zhi_p, *ehi_p;
    cudaGetSymbolAddress((void**)&zhi_p, g_zhi);
    cudaGetSymbolAddress((void**)&ehi_p, g_ehi);

    const int VQ_SMEM = NSTAGE * STAGE + 256;       // 82176
    cudaFuncSetAttribute(vq_pass1_kernel, cudaFuncAttributeMaxDynamicSharedMemorySize, VQ_SMEM);

    tobf16_kernel<<<2048, 256>>>(z, zhi_p, NROWS * DIM / 4);
    tobf16_kernel<<<1536, 256>>>(emb, ehi_p, KC * DIM / 4);
    rownorm_kernel<<<KC / 8, 256>>>(emb, KC, 0);
    rownorm_kernel<<<NROWS / 8, 256>>>(z, NROWS, 1);
    zero_loss_kernel<<<1, 1>>>();
    vq_pass1_kernel<<<NROWS / BM, 256, VQ_SMEM>>>();
    refine_kernel<<<NROWS / 8, 256>>>(z, emb, idsf, zq);
    finalize_kernel<<<1, 1>>>(lossp);
}

// round 5
// speedup vs baseline: 7.7829x; 1.1552x over previous
#include <cuda_runtime.h>
#include <cuda_bf16.h>
#include <cstdint>
#include <climits>

#define DIM    768
#define KC     2048
#define NROWS  16384
#define BM     64
#define BN     256
#define BK     32
#define CHUNKS (DIM / BK)        // 24
#define NTILE  (KC / BN)         // 8
#define TOT    (NTILE * CHUNKS)  // 192
#define STAGE  20480             // A 4KB + B 16KB
#define MARGIN 5e-4f
#define QSCALE 131072.0f
#define QTHR_Q 85                // refine candidate window in quanta (~6.5e-4)

__device__ float g_enorm[KC];
__device__ float g_zsum[NROWS];
__device__ float g_loss;
__device__ int   g_nwork;
__device__ int   g_work[NROWS];
__device__ __nv_bfloat16 g_zhi[(size_t)NROWS * DIM];
__device__ __nv_bfloat16 g_ehi[(size_t)KC * DIM];
__device__ short g_si[(size_t)NROWS * KC];     // 64 MiB quantized scores

static __device__ __forceinline__ uint32_t smem_u32(const void* p) {
    uint32_t a;
    asm("{ .reg .u64 t; cvta.to.shared.u64 t, %1; cvt.u32.u64 %0, t; }" : "=r"(a) : "l"(p));
    return a;
}
#define CP_ASYNC16(dst, src) \
    asm volatile("cp.async.cg.shared.global [%0], [%1], 16;" :: "r"(dst), "l"(src))
#define CP_COMMIT() asm volatile("cp.async.commit_group;" ::: "memory")
#define LDMX4(r, addr) \
    asm volatile("ldmatrix.sync.aligned.m8n8.x4.shared.b16 {%0,%1,%2,%3}, [%4];" \
        : "=r"((r)[0]), "=r"((r)[1]), "=r"((r)[2]), "=r"((r)[3]) : "r"(addr))
#define MMA16816(d, a, b0_, b1_) \
    asm volatile("mma.sync.aligned.m16n8k16.row.col.f32.bf16.bf16.f32 " \
        "{%0,%1,%2,%3}, {%4,%5,%6,%7}, {%8,%9}, {%0,%1,%2,%3};" \
        : "+f"((d)[0]), "+f"((d)[1]), "+f"((d)[2]), "+f"((d)[3]) \
        : "r"((a)[0]), "r"((a)[1]), "r"((a)[2]), "r"((a)[3]), "r"(b0_), "r"(b1_))

// ---------------- fused fp32->bf16 convert + row squared-norm (warp/row) ----------------
__global__ void prep_kernel(const float* __restrict__ src,
                            __nv_bfloat16* __restrict__ dst,
                            float* __restrict__ norms, int nrows) {
    int w    = (blockIdx.x * blockDim.x + threadIdx.x) >> 5;
    int lane = threadIdx.x & 31;
    if (w >= nrows) return;
    const float2* s2 = (const float2*)(src + (size_t)w * DIM);
    __nv_bfloat162* d2 = (__nv_bfloat162*)(dst + (size_t)w * DIM);
    float acc = 0.f;
#pragma unroll
    for (int j = 0; j < DIM / 64; j++) {        // 12
        float2 v = s2[lane + j * 32];
        acc = fmaf(v.x, v.x, fmaf(v.y, v.y, acc));
        d2[lane + j * 32] = __halves2bfloat162(__float2bfloat16_rn(v.x),
                                               __float2bfloat16_rn(v.y));
    }
#pragma unroll
    for (int o = 16; o > 0; o >>= 1) acc += __shfl_down_sync(0xffffffffu, acc, o);
    if (lane == 0) norms[w] = acc;
}

__global__ void zero_kernel() { g_loss = 0.f; g_nwork = 0; }

// ---------------- pass 1: approx GEMM + in-kernel top-2 argmin ----------------
// 256 CTAs x 256 thr. CTA: 64 rows x 2048 codes. Warps 2x4, warp tile 32x64.
__global__ __launch_bounds__(256, 2)
void vq_pass1_kernel(float* __restrict__ ids_out) {
    extern __shared__ char smem_raw[];
    const uint32_t sb = (smem_u32(smem_raw) + 127u) & ~127u;
    const int tid  = threadIdx.x;
    const int lane = tid & 31;
    const int w    = tid >> 5;
    const int wr   = w >> 2;    // 0..1  rows 32 each
    const int wc   = w & 3;     // 0..3  cols 64 each
    const int rowBase = blockIdx.x * BM;

    // ---- cp.async: 5 x 16B per thread per stage ----
    uint32_t sdst[5];
    const __nv_bfloat16* gptr[5];
    bool isB[5];
#pragma unroll
    for (int i = 0; i < 5; i++) {
        int idx = i * 256 + tid;
        if (idx < 256) {
            int r = idx >> 2, g = idx & 3;
            sdst[i] = (uint32_t)(r * 64 + ((g ^ ((r >> 1) & 3)) << 4));
            gptr[i] = g_zhi + (size_t)(rowBase + r) * DIM + g * 8;
            isB[i] = false;
        } else {
            int j = idx - 256;
            int r = j >> 2, g = j & 3;
            sdst[i] = (uint32_t)(4096 + r * 64 + ((g ^ ((r >> 1) & 3)) << 4));
            gptr[i] = g_ehi + (size_t)r * DIM + g * 8;
            isB[i] = true;
        }
    }

    // ---- ldmatrix lane addressing ----
    const int arow = lane & 15;
    const int agr  = lane >> 4;
    const int brow = (lane & 7) + ((lane >> 4) & 1) * 8;
    const int bgr  = (lane >> 3) & 1;
    uint32_t a_rt[2]; int a_sw[2];
#pragma unroll
    for (int mt = 0; mt < 2; mt++) {
        int r = wr * 32 + mt * 16 + arow;
        a_rt[mt] = r * 64; a_sw[mt] = (r >> 1) & 3;
    }
    uint32_t b_rt[4]; int b_sw[4];
#pragma unroll
    for (int nh = 0; nh < 4; nh++) {
        int r = wc * 64 + nh * 16 + brow;
        b_rt[nh] = r * 64; b_sw[nh] = (r >> 1) & 3;
    }

    float acc[2][8][4];
#pragma unroll
    for (int mt = 0; mt < 2; mt++)
#pragma unroll
        for (int nt = 0; nt < 8; nt++)
#pragma unroll
            for (int q = 0; q < 4; q++) acc[mt][nt][q] = 0.f;

    // per-thread top-2 per row-slot (slot = mt*2+h)
    float v1[4], v2[4], zr4[4];
    int   i1[4];
#pragma unroll
    for (int sl = 0; sl < 4; sl++) {
        v1[sl] = 3.4e38f; v2[sl] = 3.4e38f; i1[sl] = 0;
        zr4[sl] = g_zsum[rowBase + wr * 32 + (sl >> 1) * 16 + (sl & 1) * 8 + (lane >> 2)];
    }

    auto issue = [&](int ct, int c, int buf) {
        uint32_t st = sb + buf * STAGE;
        size_t k0 = (size_t)c * BK;
        size_t bo = (size_t)ct * BN * DIM + k0;
#pragma unroll
        for (int i = 0; i < 5; i++) {
            const __nv_bfloat16* src = gptr[i] + (isB[i] ? bo : k0);
            CP_ASYNC16(st + sdst[i], src);
        }
        CP_COMMIT();
    };

    issue(0, 0, 0);
    issue(0, 1, 1);
    issue(0, 2, 2);
    int cct = 0, ccc = 0;

    for (int s = 0; s < TOT; s++) {
        if (s >= TOT - 3) asm volatile("cp.async.wait_group 0;" ::: "memory");
        else              asm volatile("cp.async.wait_group 2;" ::: "memory");
        __syncthreads();
        int nx = s + 3;
        if (nx < TOT) issue(nx / CHUNKS, nx % CHUNKS, nx & 3);

        const uint32_t Ab = sb + (s & 3) * STAGE;
        const uint32_t Bb = Ab + 4096;

#pragma unroll
        for (int ks = 0; ks < 2; ks++) {
            const int g0 = ks * 2;
            uint32_t ah[8], bh[16];
#pragma unroll
            for (int mt = 0; mt < 2; mt++) {
                uint32_t ad = Ab + a_rt[mt] + (uint32_t)(((g0 + agr) ^ a_sw[mt]) << 4);
                LDMX4(&ah[mt * 4], ad);
            }
#pragma unroll
            for (int nh = 0; nh < 4; nh++) {
                uint32_t bd = Bb + b_rt[nh] + (uint32_t)(((g0 + bgr) ^ b_sw[nh]) << 4);
                LDMX4(&bh[nh * 4], bd);
            }
#pragma unroll
            for (int mt = 0; mt < 2; mt++)
#pragma unroll
                for (int nt = 0; nt < 8; nt++) {
                    const int bo_ = (nt >> 1) * 4 + (nt & 1) * 2;
                    MMA16816(acc[mt][nt], &ah[mt * 4], bh[bo_], bh[bo_ + 1]);
                }
        }

        // ---- tile end: top-2 update + int16 score store ----
        if (ccc == CHUNKS - 1) {
#pragma unroll
            for (int nt = 0; nt < 8; nt++) {
                int cb = cct * BN + wc * 64 + nt * 8 + (lane & 3) * 2;
                float e0 = __ldg(&g_enorm[cb]);
                float e1 = __ldg(&g_enorm[cb + 1]);
#pragma unroll
                for (int mt = 0; mt < 2; mt++)
#pragma unroll
                    for (int h = 0; h < 2; h++) {
                        const int sl = mt * 2 + h;
                        float d0 = acc[mt][nt][h * 2], d1 = acc[mt][nt][h * 2 + 1];
                        // reference rounding: fl(fl(zsum+enorm) - 2*dot)
                        float s0 = (zr4[sl] + e0) - 2.0f * d0;
                        float s1 = (zr4[sl] + e1) - 2.0f * d1;
                        if (s0 < v1[sl]) { v2[sl] = v1[sl]; v1[sl] = s0; i1[sl] = cb; }
                        else if (s0 < v2[sl]) v2[sl] = s0;
                        if (s1 < v1[sl]) { v2[sl] = v1[sl]; v1[sl] = s1; i1[sl] = cb + 1; }
                        else if (s1 < v2[sl]) v2[sl] = s1;
                        int q0 = __float2int_rn(fminf(fmaxf((e0 - 2.0f * d0) * QSCALE, -32767.f), 32767.f));
                        int q1 = __float2int_rn(fminf(fmaxf((e1 - 2.0f * d1) * QSCALE, -32767.f), 32767.f));
                        int row0 = rowBase + wr * 32 + mt * 16 + h * 8 + (lane >> 2);
                        *(short2*)&g_si[(size_t)row0 * KC + cb] =
                            make_short2((short)q0, (short)q1);
                        acc[mt][nt][h * 2] = 0.f;
                        acc[mt][nt][h * 2 + 1] = 0.f;
                    }
            }
        }
        if (++ccc == CHUNKS) { ccc = 0; ++cct; }
    }

    // ---- cross-thread top-2 merge (first-index ties) ----
#pragma unroll
    for (int off = 1; off <= 2; off <<= 1) {
#pragma unroll
        for (int sl = 0; sl < 4; sl++) {
            float ov1 = __shfl_xor_sync(0xffffffffu, v1[sl], off);
            float ov2 = __shfl_xor_sync(0xffffffffu, v2[sl], off);
            int   oi1 = __shfl_xor_sync(0xffffffffu, i1[sl], off);
            if (ov1 < v1[sl] || (ov1 == v1[sl] && oi1 < i1[sl])) {
                v2[sl] = fminf(v1[sl], ov2); v1[sl] = ov1; i1[sl] = oi1;
            } else {
                v2[sl] = fminf(ov1, v2[sl]);
            }
        }
    }
    __syncthreads();                 // stage buffers dead; reuse for reduction
    float* rv1 = (float*)smem_raw;
    float* rv2 = rv1 + 256;
    int*   ri1 = (int*)(rv2 + 256);
    if ((lane & 3) == 0) {
#pragma unroll
        for (int sl = 0; sl < 4; sl++) {
            int rl = wr * 32 + (sl >> 1) * 16 + (sl & 1) * 8 + (lane >> 2);
            rv1[rl * 4 + wc] = v1[sl];
            rv2[rl * 4 + wc] = v2[sl];
            ri1[rl * 4 + wc] = i1[sl];
        }
    }
    __syncthreads();
    if (tid < BM) {
        float b1 = rv1[tid * 4], b2 = rv2[tid * 4];
        int   bi = ri1[tid * 4];
#pragma unroll
        for (int t = 1; t < 4; t++) {
            float o1 = rv1[tid * 4 + t], o2 = rv2[tid * 4 + t];
            int   oi = ri1[tid * 4 + t];
            if (o1 < b1 || (o1 == b1 && oi < bi)) { b2 = fminf(b1, o2); b1 = o1; bi = oi; }
            else b2 = fminf(o1, b2);
        }
        ids_out[rowBase + tid] = (float)bi;
        if (b2 <= b1 + MARGIN) {
            int k = atomicAdd(&g_nwork, 1);
            g_work[k] = rowBase + tid;
        }
    }
}

// ---------------- refine: ambiguous rows only (warp per row) ----------------
__global__ __launch_bounds__(256)
void refine_kernel(const float* __restrict__ z, const float* __restrict__ emb,
                   float* __restrict__ ids_out) {
    const int nwork = g_nwork;
    const int lane  = threadIdx.x & 31;
    const int wg0   = (blockIdx.x * blockDim.x + threadIdx.x) >> 5;
    const int wstr  = (gridDim.x * blockDim.x) >> 5;
    for (int wi = wg0; wi < nwork; wi += wstr) {
        const int r = g_work[wi];
        const short* qr = g_si + (size_t)r * KC;
        const float zr = g_zsum[r];
        // min scan over quantized scores
        int qmin = INT_MAX;
        const short2* q2 = (const short2*)qr;
#pragma unroll 8
        for (int j = 0; j < 32; j++) {
            short2 p = q2[lane + j * 32];
            qmin = min(qmin, min((int)p.x, (int)p.y));
        }
#pragma unroll
        for (int o = 16; o > 0; o >>= 1)
            qmin = min(qmin, __shfl_xor_sync(0xffffffffu, qmin, o));
        const int qthr = qmin + QTHR_Q;

        // z row in registers (exact fp32)
        float zreg[24];
        const float* zrow = z + (size_t)r * DIM;
#pragma unroll
        for (int j = 0; j < 24; j++) zreg[j] = zrow[lane + j * 32];

        float best = 3.4e38f;
        int   bi   = INT_MAX;
        for (int k = 0; k < 64; k++) {
            int c = k * 32 + lane;
            unsigned mask = __ballot_sync(0xffffffffu, (int)qr[c] <= qthr);
            while (mask) {
                int l = __ffs(mask) - 1;
                mask &= mask - 1;
                int cc = k * 32 + l;
                const float* erow = emb + (size_t)cc * DIM;
                float d = 0.f;
#pragma unroll
                for (int j = 0; j < 24; j++) d = fmaf(zreg[j], erow[lane + j * 32], d);
#pragma unroll
                for (int o = 16; o > 0; o >>= 1) d += __shfl_xor_sync(0xffffffffu, d, o);
                float se = (zr + g_enorm[cc]) - 2.0f * d;   // reference rounding
                if (se < best || (se == best && cc < bi)) { best = se; bi = cc; }
            }
        }
        if (lane == 0) ids_out[r] = (float)bi;
    }
}

// ---------------- gather z_q + commitment loss (warp per row) ----------------
__global__ __launch_bounds__(256)
void gather_loss_kernel(const float* __restrict__ z, const float* __restrict__ emb,
                        const float* __restrict__ idsf, float* __restrict__ zq) {
    __shared__ float redl[8];
    const int w    = threadIdx.x >> 5;
    const int lane = threadIdx.x & 31;
    const int r    = blockIdx.x * 8 + w;
    const int id   = (int)idsf[r];
    const float* zrow = z + (size_t)r * DIM;
    const float* erow = emb + (size_t)id * DIM;
    float* qrow = zq + (size_t)r * DIM;
    float lacc = 0.f;
#pragma unroll
    for (int j = 0; j < 24; j++) {
        float q  = erow[lane + j * 32];
        float zv = zrow[lane + j * 32];
        qrow[lane + j * 32] = q;
        float dd = zv - q;
        lacc = fmaf(dd, dd, lacc);
    }
#pragma unroll
    for (int o = 16; o > 0; o >>= 1) lacc += __shfl_down_sync(0xffffffffu, lacc, o);
    if (lane == 0) redl[w] = lacc;
    __syncthreads();
    if (threadIdx.x == 0) {
        float t = 0.f;
#pragma unroll
        for (int i = 0; i < 8; i++) t += redl[i];
        atomicAdd(&g_loss, t);
    }
}

__global__ void finalize_kernel(float* __restrict__ loss_out) {
    *loss_out = 0.25f * (g_loss / (float)((long long)NROWS * DIM));
}

// ---------------- launch ----------------
extern "C" void kernel_launch(void* const* d_in, const int* in_sizes, int n_in,
                              void* d_out, int out_size) {
    (void)in_sizes; (void)n_in; (void)out_size;
    const float* z   = (const float*)d_in[0];
    const float* emb = (const float*)d_in[1];
    float* out   = (float*)d_out;
    float* zq    = out;                              // [NROWS*DIM]
    float* idsf  = out + (size_t)NROWS * DIM;        // [NROWS]
    float* lossp = idsf + NROWS;                     // [1]

    __nv_bfloat16 *zhi_p, *ehi_p;
    float *zsum_p, *enorm_p;
    cudaGetSymbolAddress((void**)&zhi_p, g_zhi);
    cudaGetSymbolAddress((void**)&ehi_p, g_ehi);
    cudaGetSymbolAddress((void**)&zsum_p, g_zsum);
    cudaGetSymbolAddress((void**)&enorm_p, g_enorm);

    const int VQ_SMEM = 4 * STAGE + 256;            // 82176
    cudaFuncSetAttribute(vq_pass1_kernel, cudaFuncAttributeMaxDynamicSharedMemorySize, VQ_SMEM);

    prep_kernel<<<NROWS / 8, 256>>>(z, zhi_p, zsum_p, NROWS);
    prep_kernel<<<KC / 8, 256>>>(emb, ehi_p, enorm_p, KC);
    zero_kernel<<<1, 1>>>();
    vq_pass1_kernel<<<NROWS / BM, 256, VQ_SMEM>>>(idsf);
    refine_kernel<<<512, 256>>>(z, emb, idsf);
    gather_loss_kernel<<<NROWS / 8, 256>>>(z, emb, idsf, zq);
    finalize_kernel<<<1, 1>>>(lossp);
}